// round 9
// baseline (speedup 1.0000x reference)
#include <cuda_runtime.h>
#include <cuda_bf16.h>
#include <math.h>

#define TOKS 8192
#define ELEMS 1048576
typedef unsigned long long ull;
typedef unsigned int u32;
typedef unsigned short u16;

// ---------------- scratch ----------------
__device__ float g_h[ELEMS];
__device__ float g_h2[ELEMS];
__device__ float g_a[ELEMS];
__device__ float g_qkv[3*ELEMS];
__device__ u32 g_wB[10*16384];      // weights in B-frag order, hi/lo split
__device__ u32 g_kvF[2*128*8192];   // K,V frags per (b,h)

// ---------------- helpers ----------------
__device__ __forceinline__ u16 bfhi(float v) {
    return __bfloat16_as_ushort(__float2bfloat16_rn(v));
}
__device__ __forceinline__ float bf2f(u16 u) {
    return __bfloat162float(__ushort_as_bfloat16(u));
}
__device__ __forceinline__ float ex2f(float x) {
    float r; asm("ex2.approx.f32 %0, %1;" : "=f"(r) : "f"(x)); return r;
}
__device__ __forceinline__ u32 cvtbf2(float hi, float lo) {
    u32 r; asm("cvt.rn.bf16x2.f32 %0, %1, %2;" : "=r"(r) : "f"(hi), "f"(lo)); return r;
}
__device__ __forceinline__ void mma16816(float4& c, const uint4& a, const uint2& b) {
    asm("mma.sync.aligned.m16n8k16.row.col.f32.bf16.bf16.f32 "
        "{%0,%1,%2,%3}, {%4,%5,%6,%7}, {%8,%9}, {%0,%1,%2,%3};"
        : "+f"(c.x), "+f"(c.y), "+f"(c.z), "+f"(c.w)
        : "r"(a.x), "r"(a.y), "r"(a.z), "r"(a.w), "r"(b.x), "r"(b.y));
}
__device__ __forceinline__ void split2(float f0, float f1, u32& hi, u32& lo) {
    hi = cvtbf2(f1, f0);
    float h0 = __uint_as_float(hi << 16);
    float h1 = __uint_as_float(hi & 0xFFFF0000u);
    lo = cvtbf2(f1 - h1, f0 - h0);
}

// ---------------- weight prep ----------------
__global__ void prep_weights(const float* __restrict__ Wq, const float* __restrict__ Wk,
                             const float* __restrict__ Wv, const float* __restrict__ pw,
                             const float* __restrict__ f1, const float* __restrict__ f2,
                             const float* __restrict__ Wo, u32* __restrict__ wB) {
    int idx = blockIdx.x*256 + threadIdx.x;          // 10*16384
    if (idx >= 10*16384) return;
    int j = idx >> 14, r = idx & 16383;
    int k = r >> 7, n = r & 127;
    float v;
    if (j < 3) {
        const float* W = (j==0) ? Wq : (j==1) ? Wk : Wv;   // (H,128,16)
        v = W[(n>>4)*2048 + k*16 + (n&15)];
    } else if (j < 7) {
        v = pw[(j-3)*16384 + n*128 + k];
    } else if (j < 9) {
        const float* W = (j==7) ? f1 : f2;
        v = W[n*128 + k];
    } else {
        v = Wo[k*128 + n];
    }
    u16 h = bfhi(v);
    u16 l = bfhi(v - bf2f(h));
    int kt = k >> 4, kk = k & 15;
    int reg = kk >> 3, tig = (kk & 7) >> 1, bb = kk & 1;
    int nt = n >> 3, lane = (n & 7)*4 + tig;
    u16* w16 = (u16*)(wB + (size_t)j*16384);
    int i32h = ((kt*16 + nt)*32 + lane)*2 + reg;
    int i32l = (((8 + kt)*16 + nt)*32 + lane)*2 + reg;
    w16[i32h*2 + bb] = h;
    w16[i32l*2 + bb] = l;
}

// ---------------- addpos + LN0 ----------------
__global__ __launch_bounds__(512) void addpos_ln(const float* __restrict__ x,
                                                 float* __restrict__ out, float* __restrict__ hout,
                                                 const float* __restrict__ lnS,
                                                 const float* __restrict__ lnB) {
    int m0 = blockIdx.x * 64;
    int lane = threadIdx.x & 31, warp = threadIdx.x >> 5;
    int col = lane * 4;
    const float inc = 0.14619588050756158f;   // log(10000)/63
    float4 g4 = *(const float4*)&lnS[col];
    float4 b4 = *(const float4*)&lnB[col];
    #pragma unroll
    for (int i = 0; i < 4; i++) {
        int m = m0 + warp*4 + i;
        int s = m & 511;
        float4 xv = *(const float4*)&x[m*128 + col];
        float v[4] = {xv.x, xv.y, xv.z, xv.w};
        #pragma unroll
        for (int jj = 0; jj < 4; jj++) {
            int d = col + jj;
            int dd = d & 63;
            float a = (float)s * expf(-inc*(float)dd);
            v[jj] += (d < 64) ? sinf(a) : cosf(a);
        }
        float rs_ = v[0]+v[1]+v[2]+v[3];
        float rq  = v[0]*v[0]+v[1]*v[1]+v[2]*v[2]+v[3]*v[3];
        #pragma unroll
        for (int o = 16; o > 0; o >>= 1) {
            rs_ += __shfl_xor_sync(0xffffffffu, rs_, o);
            rq  += __shfl_xor_sync(0xffffffffu, rq,  o);
        }
        float mu  = rs_ * (1.0f/128.0f);
        float var = rq  * (1.0f/128.0f) - mu*mu;
        float rinv = rsqrtf(var + 1e-5f);
        float4 ov = {v[0], v[1], v[2], v[3]};
        *(float4*)&out[m*128 + col] = ov;
        float4 hv;
        hv.x = (v[0]-mu)*rinv*g4.x + b4.x;
        hv.y = (v[1]-mu)*rinv*g4.y + b4.y;
        hv.z = (v[2]-mu)*rinv*g4.z + b4.z;
        hv.w = (v[3]-mu)*rinv*g4.w + b4.w;
        *(float4*)&hout[m*128 + col] = hv;
    }
}

// ---------------- tensor-core GEMM: 32xM tile, K=128, N=128, 256 thr ----------------
// B fragments streamed straight from gmem (L2-resident); smem = A frags / C bounce only
template<bool DW, bool MULTI, int BIASM, bool RELU, bool RES, bool LN>
__global__ __launch_bounds__(256) void gemmT(
    const float* __restrict__ A, const u32* __restrict__ Wf,
    const float* __restrict__ bias, const float* __restrict__ res,
    float* __restrict__ out, float* __restrict__ hout,
    const float* __restrict__ lnS, const float* __restrict__ lnB,
    const float* __restrict__ dww, const float* __restrict__ dwb)
{
    extern __shared__ u32 smu[];
    u32* A32 = smu;                 // 4096 u32 (16 KB)
    float* Csm = (float*)smu;       // 32 x 132 f32 (aliased; used after sync)
    if (MULTI) { Wf += blockIdx.y * 16384; out += (size_t)blockIdx.y * ELEMS; }

    int m0 = blockIdx.x * 32;
    int t = threadIdx.x, lane = t & 31, warp = t >> 5;

    u16* A16 = (u16*)A32;
    if (DW) {
        int d = t & 127, q = t >> 7;       // q in {0,1}, 16 tokens each
        float wr[7];
        #pragma unroll
        for (int kk = 0; kk < 7; kk++) wr[kk] = dww[d*7 + kk];
        float db = dwb[d];
        int kt = d >> 4;
        int tig = (d & 7) >> 1, bb = d & 1;
        int kreg2 = ((d & 15) >> 3) * 2;
        const float* hb = A + (size_t)(m0 & ~511) * 128;
        int sBase = (m0 & 511) + q*16;
        float hwin[22];
        #pragma unroll
        for (int jj = 0; jj < 22; jj++) {
            int s = sBase + jj - 3;
            hwin[jj] = (s >= 0 && s < 512) ? hb[s*128 + d] : 0.f;
        }
        #pragma unroll
        for (int i = 0; i < 16; i++) {
            float acc = db;
            #pragma unroll
            for (int kk = 0; kk < 7; kk++) acc += wr[kk] * hwin[i+kk];
            int ml = q*16 + i;
            int mt = ml >> 4, mm = ml & 15;
            int g = mm & 7, hi8 = mm >> 3;
            int reg = hi8 + kreg2;
            int ln2 = g*4 + tig;
            u16 h = bfhi(acc);
            u16 l = bfhi(acc - bf2f(h));
            int ih = ((mt*8 + kt)*32 + ln2)*4 + reg;
            int il = (((2 + mt)*8 + kt)*32 + ln2)*4 + reg;
            A16[ih*2 + bb] = h;
            A16[il*2 + bb] = l;
        }
    } else {
        #pragma unroll
        for (int i = 0; i < 4; i++) {
            int idx4 = i*256 + t;
            int m = idx4 >> 5;                  // 0..31
            int k0 = (idx4 & 31) * 4;
            float4 v = *(const float4*)&A[(size_t)(m0 + m)*128 + k0];
            float vv[4] = {v.x, v.y, v.z, v.w};
            int mt = m >> 4, mm = m & 15;
            int g = mm & 7, hi8 = mm >> 3;
            int kt = k0 >> 4;
            #pragma unroll
            for (int j = 0; j < 4; j += 2) {
                int k = k0 + j;
                int tig = (k & 7) >> 1;
                int reg = hi8 + 2*((k & 15) >> 3);
                int ln2 = g*4 + tig;
                u32 hi, lo;
                split2(vv[j], vv[j+1], hi, lo);
                A32[((mt*8 + kt)*32 + ln2)*4 + reg]     = hi;
                A32[(((2+mt)*8 + kt)*32 + ln2)*4 + reg] = lo;
            }
        }
    }
    __syncthreads();

    // mainloop: warp = (wm in 0..1, wn in 0..3); B frags LDG'd from L2
    int wm = warp >> 2, wn = warp & 3;
    int nt0 = wn*4;
    float4 acc[4];
    #pragma unroll
    for (int j = 0; j < 4; j++) acc[j] = make_float4(0.f,0.f,0.f,0.f);

    const u32* WhiB = Wf + (size_t)(nt0*32 + lane)*2;
    const u32* WloB = WhiB + 8192;   // lo split lives at +8192 u32 within the matrix

    #pragma unroll
    for (int kt = 0; kt < 8; kt++) {
        uint4 ah = *(const uint4*)&A32[((wm*8 + kt)*32 + lane)*4];
        uint4 al = *(const uint4*)&A32[(((2+wm)*8 + kt)*32 + lane)*4];
        uint2 bh[4], bl[4];
        #pragma unroll
        for (int j = 0; j < 4; j++) {
            bh[j] = *(const uint2*)&WhiB[(kt*16 + j)*64];
            bl[j] = *(const uint2*)&WloB[(kt*16 + j)*64];
        }
        #pragma unroll
        for (int j = 0; j < 4; j++) {
            mma16816(acc[j], ah, bh[j]);
            mma16816(acc[j], ah, bl[j]);
            mma16816(acc[j], al, bh[j]);
        }
    }
    __syncthreads();

    #pragma unroll
    for (int j = 0; j < 4; j++) {
        int row = wm*16 + (lane >> 2);
        int col = (nt0+j)*8 + (lane & 3)*2;
        float2 lo = {acc[j].x, acc[j].y};
        float2 hi = {acc[j].z, acc[j].w};
        *(float2*)&Csm[row*132 + col]     = lo;
        *(float2*)&Csm[(row+8)*132 + col] = hi;
    }
    __syncthreads();

    int colE = lane*4;
    float4 bv = {0,0,0,0};
    if (BIASM == 1) bv = *(const float4*)&bias[colE];
    float bs = (BIASM == 2) ? bias[0] : 0.f;
    float4 g4 = {0,0,0,0}, lb4 = {0,0,0,0};
    if (LN) { g4 = *(const float4*)&lnS[colE]; lb4 = *(const float4*)&lnB[colE]; }

    #pragma unroll
    for (int i = 0; i < 4; i++) {
        int row = warp*4 + i;
        int m = m0 + row;
        float4 c4 = *(const float4*)&Csm[row*132 + colE];
        float v[4] = {c4.x, c4.y, c4.z, c4.w};
        #pragma unroll
        for (int jj = 0; jj < 4; jj++) {
            float val = v[jj];
            if (BIASM == 1) val += ((const float*)&bv)[jj];
            if (BIASM == 2) val += bs;
            if (RELU) val = fmaxf(val, 0.f);
            v[jj] = val;
        }
        if (RES) {
            float4 r4 = *(const float4*)&res[(size_t)m*128 + colE];
            v[0] += r4.x; v[1] += r4.y; v[2] += r4.z; v[3] += r4.w;
        }
        float4 ov = {v[0], v[1], v[2], v[3]};
        *(float4*)&out[(size_t)m*128 + colE] = ov;
        if (LN) {
            float rs_ = v[0]+v[1]+v[2]+v[3];
            float rq  = v[0]*v[0]+v[1]*v[1]+v[2]*v[2]+v[3]*v[3];
            #pragma unroll
            for (int o = 16; o > 0; o >>= 1) {
                rs_ += __shfl_xor_sync(0xffffffffu, rs_, o);
                rq  += __shfl_xor_sync(0xffffffffu, rq,  o);
            }
            float mu  = rs_ * (1.0f/128.0f);
            float var = rq  * (1.0f/128.0f) - mu*mu;
            float rinv = rsqrtf(var + 1e-5f);
            float4 hv;
            hv.x = (v[0]-mu)*rinv*g4.x + lb4.x;
            hv.y = (v[1]-mu)*rinv*g4.y + lb4.y;
            hv.z = (v[2]-mu)*rinv*g4.z + lb4.z;
            hv.w = (v[3]-mu)*rinv*g4.w + lb4.w;
            *(float4*)&hout[(size_t)m*128 + colE] = hv;
        }
    }
}

// ---------------- repack K,V into mma B-fragments (hi/lo split) ----------------
__global__ __launch_bounds__(256) void kvRepack(const float* __restrict__ qkv,
                                                u32* __restrict__ kvF) {
    __shared__ u32 st[8192];
    int mat = blockIdx.x;                 // 0=K, 1=V
    int bh = blockIdx.y;
    int b = bh >> 3, h = bh & 7;
    const float* src = qkv + (size_t)(1 + mat)*ELEMS;
    int t = threadIdx.x;
    int key0 = t*2;

    float v0[16], v1[16];
    const float* p0 = src + (size_t)(b*512 + key0)*128 + h*16;
    const float* p1 = p0 + 128;
    #pragma unroll
    for (int i = 0; i < 4; i++) {
        *(float4*)&v0[i*4] = *(const float4*)(p0 + i*4);
        *(float4*)&v1[i*4] = *(const float4*)(p1 + i*4);
    }

    if (mat == 0) {
        #pragma unroll
        for (int w = 0; w < 2; w++) {
            const float* vv = (w == 0) ? v0 : v1;
            int key = key0 + w;
            int nt = key >> 3;
            int laneb = (key & 7)*4;
            #pragma unroll
            for (int dp = 0; dp < 8; dp++) {
                int tig = dp & 3, reg = dp >> 2;
                u32 hi, lo;
                split2(vv[2*dp], vv[2*dp+1], hi, lo);
                int idx = ((nt*32) + laneb + tig)*2 + reg;
                st[idx] = hi; st[4096 + idx] = lo;
            }
        }
    } else {
        int kt = key0 >> 4;
        int tig = (key0 >> 1) & 3;
        int reg = (key0 & 15) >> 3;
        #pragma unroll
        for (int d = 0; d < 16; d++) {
            u32 hi, lo;
            split2(v0[d], v1[d], hi, lo);
            int nt = d >> 3, nn = d & 7;
            int idx = ((kt*2 + nt)*32 + nn*4 + tig)*2 + reg;
            st[idx] = hi; st[4096 + idx] = lo;
        }
    }
    __syncthreads();
    u32* dst = kvF + (size_t)(mat*128 + bh)*8192;
    #pragma unroll
    for (int i = 0; i < 8; i++)
        *(uint4*)&dst[i*1024 + t*4] = *(const uint4*)&st[i*1024 + t*4];
}

// ---------------- tensor-core flash attention ----------------
__global__ __launch_bounds__(128) void attnT(const float* __restrict__ qkv,
                                             const u32* __restrict__ kvF,
                                             const int* __restrict__ mask,
                                             float* __restrict__ out) {
    __shared__ float Ms[512];
    int bh = blockIdx.y;
    int b = bh >> 3, h = bh & 7;
    int qbase = blockIdx.x * 128;
    int t = threadIdx.x, lane = t & 31, warp = t >> 5;
    int c2 = (lane & 3)*2;

    #pragma unroll
    for (int i = 0; i < 4; i++) {
        int key = i*128 + t;
        Ms[key] = mask[b*512 + key] ? 0.f : -1e30f;
    }
    __syncthreads();

    const u32* Kf = kvF + (size_t)bh * 8192;
    const u32* Vf = kvF + (size_t)(128 + bh) * 8192;

    const float qsc = 0.25f * 1.4426950408889634f;
    uint4 qh[2], ql[2];
    #pragma unroll
    for (int i = 0; i < 2; i++) {
        int r = qbase + warp*32 + i*16 + (lane >> 2);
        const float* b0p = qkv + (size_t)(b*512 + r)*128 + h*16;
        const float* b1p = b0p + 8*128;
        float2 fa = *(const float2*)(b0p + c2);
        float2 fc = *(const float2*)(b0p + c2 + 8);
        float2 fb = *(const float2*)(b1p + c2);
        float2 fd = *(const float2*)(b1p + c2 + 8);
        fa.x *= qsc; fa.y *= qsc; fb.x *= qsc; fb.y *= qsc;
        fc.x *= qsc; fc.y *= qsc; fd.x *= qsc; fd.y *= qsc;
        split2(fa.x, fa.y, qh[i].x, ql[i].x);
        split2(fb.x, fb.y, qh[i].y, ql[i].y);
        split2(fc.x, fc.y, qh[i].z, ql[i].z);
        split2(fd.x, fd.y, qh[i].w, ql[i].w);
    }

    float4 oAcc[2][2];
    float lAcc[2][2];
    #pragma unroll
    for (int i = 0; i < 2; i++) {
        oAcc[i][0] = make_float4(0,0,0,0);
        oAcc[i][1] = make_float4(0,0,0,0);
        lAcc[i][0] = 0.f; lAcc[i][1] = 0.f;
    }

    for (int kb = 0; kb < 8; kb++) {
        #pragma unroll
        for (int ktl = 0; ktl < 4; ktl++) {
            int nt0 = kb*8 + ktl*2;
            uint2 kh0 = *(const uint2*)&Kf[(nt0*32 + lane)*2];
            uint2 kh1 = *(const uint2*)&Kf[((nt0+1)*32 + lane)*2];
            uint2 kl0 = *(const uint2*)&Kf[4096 + (nt0*32 + lane)*2];
            uint2 kl1 = *(const uint2*)&Kf[4096 + ((nt0+1)*32 + lane)*2];

            float4 s[2][2];
            #pragma unroll
            for (int i = 0; i < 2; i++) {
                s[i][0] = make_float4(0,0,0,0);
                s[i][1] = make_float4(0,0,0,0);
                mma16816(s[i][0], qh[i], kh0);
                mma16816(s[i][0], ql[i], kh0);
                mma16816(s[i][0], qh[i], kl0);
                mma16816(s[i][1], qh[i], kh1);
                mma16816(s[i][1], ql[i], kh1);
                mma16816(s[i][1], qh[i], kl1);
            }

            int colb = nt0*8 + c2;
            float m00 = Ms[colb],     m01 = Ms[colb+1];
            float m10 = Ms[colb+8],   m11 = Ms[colb+9];

            uint4 pah[2], pal[2];
            #pragma unroll
            for (int i = 0; i < 2; i++) {
                float px0 = ex2f(s[i][0].x + m00);
                float py0 = ex2f(s[i][0].y + m01);
                float pz0 = ex2f(s[i][0].z + m00);
                float pw0 = ex2f(s[i][0].w + m01);
                float px1 = ex2f(s[i][1].x + m10);
                float py1 = ex2f(s[i][1].y + m11);
                float pz1 = ex2f(s[i][1].z + m10);
                float pw1 = ex2f(s[i][1].w + m11);
                lAcc[i][0] += px0 + py0 + px1 + py1;
                lAcc[i][1] += pz0 + pw0 + pz1 + pw1;
                split2(px0, py0, pah[i].x, pal[i].x);
                split2(pz0, pw0, pah[i].y, pal[i].y);
                split2(px1, py1, pah[i].z, pal[i].z);
                split2(pz1, pw1, pah[i].w, pal[i].w);
            }

            int ktg = kb*4 + ktl;
            uint2 vh0 = *(const uint2*)&Vf[((ktg*2 + 0)*32 + lane)*2];
            uint2 vh1 = *(const uint2*)&Vf[((ktg*2 + 1)*32 + lane)*2];
            uint2 vl0 = *(const uint2*)&Vf[4096 + ((ktg*2 + 0)*32 + lane)*2];
            uint2 vl1 = *(const uint2*)&Vf[4096 + ((ktg*2 + 1)*32 + lane)*2];
            #pragma unroll
            for (int i = 0; i < 2; i++) {
                mma16816(oAcc[i][0], pah[i], vh0);
                mma16816(oAcc[i][0], pal[i], vh0);
                mma16816(oAcc[i][0], pah[i], vl0);
                mma16816(oAcc[i][1], pah[i], vh1);
                mma16816(oAcc[i][1], pal[i], vh1);
                mma16816(oAcc[i][1], pah[i], vl1);
            }
        }
    }

    #pragma unroll
    for (int i = 0; i < 2; i++)
        #pragma unroll
        for (int j = 0; j < 2; j++) {
            lAcc[i][j] += __shfl_xor_sync(0xffffffffu, lAcc[i][j], 1);
            lAcc[i][j] += __shfl_xor_sync(0xffffffffu, lAcc[i][j], 2);
        }

    #pragma unroll
    for (int i = 0; i < 2; i++) {
        float inv0 = 1.f / lAcc[i][0];
        float inv1 = 1.f / lAcc[i][1];
        int r = qbase + warp*32 + i*16 + (lane >> 2);
        #pragma unroll
        for (int n = 0; n < 2; n++) {
            float* op = out + (size_t)(b*512 + r)*128 + h*16 + n*8 + c2;
            float2 lo = {oAcc[i][n].x * inv0, oAcc[i][n].y * inv0};
            float2 hi = {oAcc[i][n].z * inv1, oAcc[i][n].w * inv1};
            *(float2*)op = lo;
            *(float2*)(op + 8*128) = hi;
        }
    }
}

// ---------------- launch ----------------
extern "C" void kernel_launch(void* const* d_in, const int* in_sizes, int n_in,
                              void* d_out, int out_size) {
    const float* x     = (const float*)d_in[0];
    const int*   mask  = (const int*)  d_in[1];
    const float* ln_s  = (const float*)d_in[2];
    const float* ln_b  = (const float*)d_in[3];
    const float* dw_w  = (const float*)d_in[4];
    const float* dw_b  = (const float*)d_in[5];
    const float* pw_w  = (const float*)d_in[6];
    const float* pw_b  = (const float*)d_in[7];
    const float* Wq    = (const float*)d_in[8];
    const float* Wk    = (const float*)d_in[9];
    const float* Wv    = (const float*)d_in[10];
    const float* Wo    = (const float*)d_in[11];
    const float* ab    = (const float*)d_in[12];
    const float* f1w   = (const float*)d_in[13];
    const float* f1b   = (const float*)d_in[14];
    const float* f2w   = (const float*)d_in[15];
    const float* f2b   = (const float*)d_in[16];
    float* out = (float*)d_out;

    float *hA, *hB, *aP, *qkvP;
    u32 *wBP, *kvFP;
    cudaGetSymbolAddress((void**)&hA,   g_h);
    cudaGetSymbolAddress((void**)&hB,   g_h2);
    cudaGetSymbolAddress((void**)&aP,   g_a);
    cudaGetSymbolAddress((void**)&qkvP, g_qkv);
    cudaGetSymbolAddress((void**)&wBP,  g_wB);
    cudaGetSymbolAddress((void**)&kvFP, g_kvF);

    const int GSMEM = 4224 * 4;                 // 16896 B (A frags / C bounce union)

    auto gConv = gemmT<true,  false, 1, true,  true,  true>;
    auto gQKV  = gemmT<false, true,  2, false, false, false>;
    auto gWo   = gemmT<false, false, 2, false, true,  true>;
    auto gF1   = gemmT<false, false, 1, true,  false, false>;
    auto gF2   = gemmT<false, false, 1, false, true,  false>;
    cudaFuncSetAttribute(gConv, cudaFuncAttributeMaxDynamicSharedMemorySize, GSMEM);
    cudaFuncSetAttribute(gQKV,  cudaFuncAttributeMaxDynamicSharedMemorySize, GSMEM);
    cudaFuncSetAttribute(gWo,   cudaFuncAttributeMaxDynamicSharedMemorySize, GSMEM);
    cudaFuncSetAttribute(gF1,   cudaFuncAttributeMaxDynamicSharedMemorySize, GSMEM);
    cudaFuncSetAttribute(gF2,   cudaFuncAttributeMaxDynamicSharedMemorySize, GSMEM);

    prep_weights<<<640, 256>>>(Wq, Wk, Wv, pw_w, f1w, f2w, Wo, wBP);
    addpos_ln<<<128, 512>>>(x, out, hA, ln_s, ln_b);

    float* hin = hA; float* hob = hB;
    for (int i = 0; i < 4; i++) {
        gConv<<<256, 256, GSMEM>>>(hin, wBP + (size_t)(3+i)*16384, pw_b + i*128, out, out, hob,
                                   ln_s + (i+1)*128, ln_b + (i+1)*128,
                                   dw_w + i*896, dw_b + i*128);
        float* tmp = hin; hin = hob; hob = tmp;
    }
    // hin holds LN[4](out)
    gQKV<<<dim3(256,3), 256, GSMEM>>>(hin, wBP, ab, nullptr, qkvP, nullptr,
                                      nullptr, nullptr, nullptr, nullptr);
    kvRepack<<<dim3(2,128), 256>>>(qkvP, kvFP);
    attnT<<<dim3(4,128), 128>>>(qkvP, kvFP, mask, aP);
    gWo<<<256, 256, GSMEM>>>(aP, wBP + (size_t)9*16384, ab, out, out, hob,
                             ln_s + 5*128, ln_b + 5*128, nullptr, nullptr);
    gF1<<<256, 256, GSMEM>>>(hob, wBP + (size_t)7*16384, f1b, nullptr, aP, nullptr,
                             nullptr, nullptr, nullptr, nullptr);
    gF2<<<256, 256, GSMEM>>>(aP, wBP + (size_t)8*16384, f2b, out, out, nullptr,
                             nullptr, nullptr, nullptr, nullptr);
}

// round 11
// speedup vs baseline: 1.1217x; 1.1217x over previous
#include <cuda_runtime.h>
#include <cuda_bf16.h>
#include <math.h>

#define TOKS 8192
#define ELEMS 1048576
typedef unsigned long long ull;
typedef unsigned int u32;
typedef unsigned short u16;

// ---------------- scratch ----------------
__device__ float g_h[ELEMS];
__device__ float g_h2[ELEMS];
__device__ float g_a[ELEMS];
__device__ float g_qkv[3*ELEMS];
__device__ u32 g_wB[10*16384];      // weights in B-frag order, hi/lo split
__device__ u32 g_kvF[2*128*8192];   // K,V frags per (b,h)

// ---------------- helpers ----------------
__device__ __forceinline__ u16 bfhi(float v) {
    return __bfloat16_as_ushort(__float2bfloat16_rn(v));
}
__device__ __forceinline__ float bf2f(u16 u) {
    return __bfloat162float(__ushort_as_bfloat16(u));
}
__device__ __forceinline__ float ex2f(float x) {
    float r; asm("ex2.approx.f32 %0, %1;" : "=f"(r) : "f"(x)); return r;
}
__device__ __forceinline__ u32 cvtbf2(float hi, float lo) {
    u32 r; asm("cvt.rn.bf16x2.f32 %0, %1, %2;" : "=r"(r) : "f"(hi), "f"(lo)); return r;
}
__device__ __forceinline__ void mma16816(float4& c, const uint4& a, const uint2& b) {
    asm("mma.sync.aligned.m16n8k16.row.col.f32.bf16.bf16.f32 "
        "{%0,%1,%2,%3}, {%4,%5,%6,%7}, {%8,%9}, {%0,%1,%2,%3};"
        : "+f"(c.x), "+f"(c.y), "+f"(c.z), "+f"(c.w)
        : "r"(a.x), "r"(a.y), "r"(a.z), "r"(a.w), "r"(b.x), "r"(b.y));
}
__device__ __forceinline__ void split2(float f0, float f1, u32& hi, u32& lo) {
    hi = cvtbf2(f1, f0);
    float h0 = __uint_as_float(hi << 16);
    float h1 = __uint_as_float(hi & 0xFFFF0000u);
    lo = cvtbf2(f1 - h1, f0 - h0);
}
__device__ __forceinline__ void cpasync16(u32 saddr, const void* g) {
    asm volatile("cp.async.cg.shared.global [%0], [%1], 16;" :: "r"(saddr), "l"(g));
}

// ---------------- weight prep ----------------
__global__ void prep_weights(const float* __restrict__ Wq, const float* __restrict__ Wk,
                             const float* __restrict__ Wv, const float* __restrict__ pw,
                             const float* __restrict__ f1, const float* __restrict__ f2,
                             const float* __restrict__ Wo, u32* __restrict__ wB) {
    int idx = blockIdx.x*256 + threadIdx.x;          // 10*16384
    if (idx >= 10*16384) return;
    int j = idx >> 14, r = idx & 16383;
    int k = r >> 7, n = r & 127;
    float v;
    if (j < 3) {
        const float* W = (j==0) ? Wq : (j==1) ? Wk : Wv;   // (H,128,16)
        v = W[(n>>4)*2048 + k*16 + (n&15)];
    } else if (j < 7) {
        v = pw[(j-3)*16384 + n*128 + k];
    } else if (j < 9) {
        const float* W = (j==7) ? f1 : f2;
        v = W[n*128 + k];
    } else {
        v = Wo[k*128 + n];
    }
    u16 h = bfhi(v);
    u16 l = bfhi(v - bf2f(h));
    int kt = k >> 4, kk = k & 15;
    int reg = kk >> 3, tig = (kk & 7) >> 1, bb = kk & 1;
    int nt = n >> 3, lane = (n & 7)*4 + tig;
    u16* w16 = (u16*)(wB + (size_t)j*16384);
    int i32h = ((kt*16 + nt)*32 + lane)*2 + reg;
    int i32l = (((8 + kt)*16 + nt)*32 + lane)*2 + reg;
    w16[i32h*2 + bb] = h;
    w16[i32l*2 + bb] = l;
}

// ---------------- addpos + LN0 ----------------
__global__ __launch_bounds__(512) void addpos_ln(const float* __restrict__ x,
                                                 float* __restrict__ out, float* __restrict__ hout,
                                                 const float* __restrict__ lnS,
                                                 const float* __restrict__ lnB) {
    int m0 = blockIdx.x * 64;
    int lane = threadIdx.x & 31, warp = threadIdx.x >> 5;
    int col = lane * 4;
    const float inc = 0.14619588050756158f;   // log(10000)/63
    float4 g4 = *(const float4*)&lnS[col];
    float4 b4 = *(const float4*)&lnB[col];
    #pragma unroll
    for (int i = 0; i < 4; i++) {
        int m = m0 + warp*4 + i;
        int s = m & 511;
        float4 xv = *(const float4*)&x[m*128 + col];
        float v[4] = {xv.x, xv.y, xv.z, xv.w};
        #pragma unroll
        for (int jj = 0; jj < 4; jj++) {
            int d = col + jj;
            int dd = d & 63;
            float a = (float)s * expf(-inc*(float)dd);
            v[jj] += (d < 64) ? sinf(a) : cosf(a);
        }
        float rs_ = v[0]+v[1]+v[2]+v[3];
        float rq  = v[0]*v[0]+v[1]*v[1]+v[2]*v[2]+v[3]*v[3];
        #pragma unroll
        for (int o = 16; o > 0; o >>= 1) {
            rs_ += __shfl_xor_sync(0xffffffffu, rs_, o);
            rq  += __shfl_xor_sync(0xffffffffu, rq,  o);
        }
        float mu  = rs_ * (1.0f/128.0f);
        float var = rq  * (1.0f/128.0f) - mu*mu;
        float rinv = rsqrtf(var + 1e-5f);
        float4 ov = {v[0], v[1], v[2], v[3]};
        *(float4*)&out[m*128 + col] = ov;
        float4 hv;
        hv.x = (v[0]-mu)*rinv*g4.x + b4.x;
        hv.y = (v[1]-mu)*rinv*g4.y + b4.y;
        hv.z = (v[2]-mu)*rinv*g4.z + b4.z;
        hv.w = (v[3]-mu)*rinv*g4.w + b4.w;
        *(float4*)&hout[m*128 + col] = hv;
    }
}

// ---------------- tensor-core GEMM: 32xM tile, K=128, N=128, 256 thr ----------------
// B staged into smem via cp.async, overlapped with the A producer.
// smem: B32[16384] | union(A32[4096], Csm f32[32][132])
template<bool DW, bool MULTI, int BIASM, bool RELU, bool RES, bool LN>
__global__ __launch_bounds__(256) void gemmT(
    const float* __restrict__ A, const u32* __restrict__ Wf,
    const float* __restrict__ bias, const float* __restrict__ res,
    float* __restrict__ out, float* __restrict__ hout,
    const float* __restrict__ lnS, const float* __restrict__ lnB,
    const float* __restrict__ dww, const float* __restrict__ dwb)
{
    extern __shared__ u32 smu[];
    u32* B32 = smu;                       // 16384 u32 (64 KB)
    u32* A32 = smu + 16384;               // 4096 u32
    float* Csm = (float*)(smu + 16384);   // 32 x 132 f32 (aliased with A32 region)
    if (MULTI) { Wf += blockIdx.y * 16384; out += (size_t)blockIdx.y * ELEMS; }

    int m0 = blockIdx.x * 32;
    int t = threadIdx.x, lane = t & 31, warp = t >> 5;

    // kick off B staging: 16 x 16B per thread, async into smem
    {
        u32 sbase = (u32)__cvta_generic_to_shared(&B32[t*4]);
        const u32* gsrc = Wf + t*4;
        #pragma unroll
        for (int i = 0; i < 16; i++)
            cpasync16(sbase + i*4096, gsrc + i*1024);   // 1024 u32 = 4096 B
        asm volatile("cp.async.commit_group;" ::: "memory");
    }

    // A producer overlaps with B copies
    u16* A16 = (u16*)A32;
    if (DW) {
        int d = t & 127, q = t >> 7;       // q in {0,1}, 16 tokens each
        float wr[7];
        #pragma unroll
        for (int kk = 0; kk < 7; kk++) wr[kk] = dww[d*7 + kk];
        float db = dwb[d];
        int kt = d >> 4;
        int tig = (d & 7) >> 1, bb = d & 1;
        int kreg2 = ((d & 15) >> 3) * 2;
        const float* hb = A + (size_t)(m0 & ~511) * 128;
        int sBase = (m0 & 511) + q*16;
        float hwin[22];
        #pragma unroll
        for (int jj = 0; jj < 22; jj++) {
            int s = sBase + jj - 3;
            hwin[jj] = (s >= 0 && s < 512) ? hb[s*128 + d] : 0.f;
        }
        #pragma unroll
        for (int i = 0; i < 16; i++) {
            float acc = db;
            #pragma unroll
            for (int kk = 0; kk < 7; kk++) acc += wr[kk] * hwin[i+kk];
            int ml = q*16 + i;
            int mt = ml >> 4, mm = ml & 15;
            int g = mm & 7, hi8 = mm >> 3;
            int reg = hi8 + kreg2;
            int ln2 = g*4 + tig;
            u16 h = bfhi(acc);
            u16 l = bfhi(acc - bf2f(h));
            int ih = ((mt*8 + kt)*32 + ln2)*4 + reg;
            int il = (((2 + mt)*8 + kt)*32 + ln2)*4 + reg;
            A16[ih*2 + bb] = h;
            A16[il*2 + bb] = l;
        }
    } else {
        #pragma unroll
        for (int i = 0; i < 4; i++) {
            int idx4 = i*256 + t;
            int m = idx4 >> 5;                  // 0..31
            int k0 = (idx4 & 31) * 4;
            float4 v = *(const float4*)&A[(size_t)(m0 + m)*128 + k0];
            float vv[4] = {v.x, v.y, v.z, v.w};
            int mt = m >> 4, mm = m & 15;
            int g = mm & 7, hi8 = mm >> 3;
            int kt = k0 >> 4;
            #pragma unroll
            for (int j = 0; j < 4; j += 2) {
                int k = k0 + j;
                int tig = (k & 7) >> 1;
                int reg = hi8 + 2*((k & 15) >> 3);
                int ln2 = g*4 + tig;
                u32 hi, lo;
                split2(vv[j], vv[j+1], hi, lo);
                A32[((mt*8 + kt)*32 + ln2)*4 + reg]     = hi;
                A32[(((2+mt)*8 + kt)*32 + ln2)*4 + reg] = lo;
            }
        }
    }
    asm volatile("cp.async.wait_group 0;" ::: "memory");
    __syncthreads();

    // mainloop: warp = (wm in 0..1, wn in 0..3)
    int wm = warp >> 2, wn = warp & 3;
    int nt0 = wn*4;
    float4 acc[4];
    #pragma unroll
    for (int j = 0; j < 4; j++) acc[j] = make_float4(0.f,0.f,0.f,0.f);

    #pragma unroll
    for (int kt = 0; kt < 8; kt++) {
        uint4 ah = *(const uint4*)&A32[((wm*8 + kt)*32 + lane)*4];
        uint4 al = *(const uint4*)&A32[(((2+wm)*8 + kt)*32 + lane)*4];
        uint2 bh[4], bl[4];
        #pragma unroll
        for (int j = 0; j < 4; j++) {
            bh[j] = *(const uint2*)&B32[((kt*16 + nt0+j)*32 + lane)*2];
            bl[j] = *(const uint2*)&B32[(((8+kt)*16 + nt0+j)*32 + lane)*2];
        }
        #pragma unroll
        for (int j = 0; j < 4; j++) {
            mma16816(acc[j], ah, bh[j]);
            mma16816(acc[j], ah, bl[j]);
            mma16816(acc[j], al, bh[j]);
        }
    }
    __syncthreads();

    #pragma unroll
    for (int j = 0; j < 4; j++) {
        int row = wm*16 + (lane >> 2);
        int col = (nt0+j)*8 + (lane & 3)*2;
        float2 lo = {acc[j].x, acc[j].y};
        float2 hi = {acc[j].z, acc[j].w};
        *(float2*)&Csm[row*132 + col]     = lo;
        *(float2*)&Csm[(row+8)*132 + col] = hi;
    }
    __syncthreads();

    int colE = lane*4;
    float4 bv = {0,0,0,0};
    if (BIASM == 1) bv = *(const float4*)&bias[colE];
    float bs = (BIASM == 2) ? bias[0] : 0.f;
    float4 g4 = {0,0,0,0}, lb4 = {0,0,0,0};
    if (LN) { g4 = *(const float4*)&lnS[colE]; lb4 = *(const float4*)&lnB[colE]; }

    #pragma unroll
    for (int i = 0; i < 4; i++) {
        int row = warp*4 + i;
        int m = m0 + row;
        float4 c4 = *(const float4*)&Csm[row*132 + colE];
        float v[4] = {c4.x, c4.y, c4.z, c4.w};
        #pragma unroll
        for (int jj = 0; jj < 4; jj++) {
            float val = v[jj];
            if (BIASM == 1) val += ((const float*)&bv)[jj];
            if (BIASM == 2) val += bs;
            if (RELU) val = fmaxf(val, 0.f);
            v[jj] = val;
        }
        if (RES) {
            float4 r4 = *(const float4*)&res[(size_t)m*128 + colE];
            v[0] += r4.x; v[1] += r4.y; v[2] += r4.z; v[3] += r4.w;
        }
        float4 ov = {v[0], v[1], v[2], v[3]};
        *(float4*)&out[(size_t)m*128 + colE] = ov;
        if (LN) {
            float rs_ = v[0]+v[1]+v[2]+v[3];
            float rq  = v[0]*v[0]+v[1]*v[1]+v[2]*v[2]+v[3]*v[3];
            #pragma unroll
            for (int o = 16; o > 0; o >>= 1) {
                rs_ += __shfl_xor_sync(0xffffffffu, rs_, o);
                rq  += __shfl_xor_sync(0xffffffffu, rq,  o);
            }
            float mu  = rs_ * (1.0f/128.0f);
            float var = rq  * (1.0f/128.0f) - mu*mu;
            float rinv = rsqrtf(var + 1e-5f);
            float4 hv;
            hv.x = (v[0]-mu)*rinv*g4.x + lb4.x;
            hv.y = (v[1]-mu)*rinv*g4.y + lb4.y;
            hv.z = (v[2]-mu)*rinv*g4.z + lb4.z;
            hv.w = (v[3]-mu)*rinv*g4.w + lb4.w;
            *(float4*)&hout[(size_t)m*128 + colE] = hv;
        }
    }
}

// ---------------- repack K,V into mma B-fragments (hi/lo split) ----------------
__global__ __launch_bounds__(256) void kvRepack(const float* __restrict__ qkv,
                                                u32* __restrict__ kvF) {
    __shared__ u32 st[8192];
    int mat = blockIdx.x;                 // 0=K, 1=V
    int bh = blockIdx.y;
    int b = bh >> 3, h = bh & 7;
    const float* src = qkv + (size_t)(1 + mat)*ELEMS;
    int t = threadIdx.x;
    int key0 = t*2;

    float v0[16], v1[16];
    const float* p0 = src + (size_t)(b*512 + key0)*128 + h*16;
    const float* p1 = p0 + 128;
    #pragma unroll
    for (int i = 0; i < 4; i++) {
        *(float4*)&v0[i*4] = *(const float4*)(p0 + i*4);
        *(float4*)&v1[i*4] = *(const float4*)(p1 + i*4);
    }

    if (mat == 0) {
        #pragma unroll
        for (int w = 0; w < 2; w++) {
            const float* vv = (w == 0) ? v0 : v1;
            int key = key0 + w;
            int nt = key >> 3;
            int laneb = (key & 7)*4;
            #pragma unroll
            for (int dp = 0; dp < 8; dp++) {
                int tig = dp & 3, reg = dp >> 2;
                u32 hi, lo;
                split2(vv[2*dp], vv[2*dp+1], hi, lo);
                int idx = ((nt*32) + laneb + tig)*2 + reg;
                st[idx] = hi; st[4096 + idx] = lo;
            }
        }
    } else {
        int kt = key0 >> 4;
        int tig = (key0 >> 1) & 3;
        int reg = (key0 & 15) >> 3;
        #pragma unroll
        for (int d = 0; d < 16; d++) {
            u32 hi, lo;
            split2(v0[d], v1[d], hi, lo);
            int nt = d >> 3, nn = d & 7;
            int idx = ((kt*2 + nt)*32 + nn*4 + tig)*2 + reg;
            st[idx] = hi; st[4096 + idx] = lo;
        }
    }
    __syncthreads();
    u32* dst = kvF + (size_t)(mat*128 + bh)*8192;
    #pragma unroll
    for (int i = 0; i < 8; i++)
        *(uint4*)&dst[i*1024 + t*4] = *(const uint4*)&st[i*1024 + t*4];
}

// ---------------- tensor-core flash attention ----------------
__global__ __launch_bounds__(128) void attnT(const float* __restrict__ qkv,
                                             const u32* __restrict__ kvF,
                                             const int* __restrict__ mask,
                                             float* __restrict__ out) {
    __shared__ float Ms[512];
    int bh = blockIdx.y;
    int b = bh >> 3, h = bh & 7;
    int qbase = blockIdx.x * 128;
    int t = threadIdx.x, lane = t & 31, warp = t >> 5;
    int c2 = (lane & 3)*2;

    #pragma unroll
    for (int i = 0; i < 4; i++) {
        int key = i*128 + t;
        Ms[key] = mask[b*512 + key] ? 0.f : -1e30f;
    }
    __syncthreads();

    const u32* Kf = kvF + (size_t)bh * 8192;
    const u32* Vf = kvF + (size_t)(128 + bh) * 8192;

    const float qsc = 0.25f * 1.4426950408889634f;
    uint4 qh[2], ql[2];
    #pragma unroll
    for (int i = 0; i < 2; i++) {
        int r = qbase + warp*32 + i*16 + (lane >> 2);
        const float* b0p = qkv + (size_t)(b*512 + r)*128 + h*16;
        const float* b1p = b0p + 8*128;
        float2 fa = *(const float2*)(b0p + c2);
        float2 fc = *(const float2*)(b0p + c2 + 8);
        float2 fb = *(const float2*)(b1p + c2);
        float2 fd = *(const float2*)(b1p + c2 + 8);
        fa.x *= qsc; fa.y *= qsc; fb.x *= qsc; fb.y *= qsc;
        fc.x *= qsc; fc.y *= qsc; fd.x *= qsc; fd.y *= qsc;
        split2(fa.x, fa.y, qh[i].x, ql[i].x);
        split2(fb.x, fb.y, qh[i].y, ql[i].y);
        split2(fc.x, fc.y, qh[i].z, ql[i].z);
        split2(fd.x, fd.y, qh[i].w, ql[i].w);
    }

    float4 oAcc[2][2];
    float lAcc[2][2];
    #pragma unroll
    for (int i = 0; i < 2; i++) {
        oAcc[i][0] = make_float4(0,0,0,0);
        oAcc[i][1] = make_float4(0,0,0,0);
        lAcc[i][0] = 0.f; lAcc[i][1] = 0.f;
    }

    for (int kb = 0; kb < 8; kb++) {
        #pragma unroll
        for (int ktl = 0; ktl < 4; ktl++) {
            int nt0 = kb*8 + ktl*2;
            uint2 kh0 = *(const uint2*)&Kf[(nt0*32 + lane)*2];
            uint2 kh1 = *(const uint2*)&Kf[((nt0+1)*32 + lane)*2];
            uint2 kl0 = *(const uint2*)&Kf[4096 + (nt0*32 + lane)*2];
            uint2 kl1 = *(const uint2*)&Kf[4096 + ((nt0+1)*32 + lane)*2];

            float4 s[2][2];
            #pragma unroll
            for (int i = 0; i < 2; i++) {
                s[i][0] = make_float4(0,0,0,0);
                s[i][1] = make_float4(0,0,0,0);
                mma16816(s[i][0], qh[i], kh0);
                mma16816(s[i][0], ql[i], kh0);
                mma16816(s[i][0], qh[i], kl0);
                mma16816(s[i][1], qh[i], kh1);
                mma16816(s[i][1], ql[i], kh1);
                mma16816(s[i][1], qh[i], kl1);
            }

            int colb = nt0*8 + c2;
            float m00 = Ms[colb],     m01 = Ms[colb+1];
            float m10 = Ms[colb+8],   m11 = Ms[colb+9];

            uint4 pah[2], pal[2];
            #pragma unroll
            for (int i = 0; i < 2; i++) {
                float px0 = ex2f(s[i][0].x + m00);
                float py0 = ex2f(s[i][0].y + m01);
                float pz0 = ex2f(s[i][0].z + m00);
                float pw0 = ex2f(s[i][0].w + m01);
                float px1 = ex2f(s[i][1].x + m10);
                float py1 = ex2f(s[i][1].y + m11);
                float pz1 = ex2f(s[i][1].z + m10);
                float pw1 = ex2f(s[i][1].w + m11);
                lAcc[i][0] += px0 + py0 + px1 + py1;
                lAcc[i][1] += pz0 + pw0 + pz1 + pw1;
                split2(px0, py0, pah[i].x, pal[i].x);
                split2(pz0, pw0, pah[i].y, pal[i].y);
                split2(px1, py1, pah[i].z, pal[i].z);
                split2(pz1, pw1, pah[i].w, pal[i].w);
            }

            int ktg = kb*4 + ktl;
            uint2 vh0 = *(const uint2*)&Vf[((ktg*2 + 0)*32 + lane)*2];
            uint2 vh1 = *(const uint2*)&Vf[((ktg*2 + 1)*32 + lane)*2];
            uint2 vl0 = *(const uint2*)&Vf[4096 + ((ktg*2 + 0)*32 + lane)*2];
            uint2 vl1 = *(const uint2*)&Vf[4096 + ((ktg*2 + 1)*32 + lane)*2];
            #pragma unroll
            for (int i = 0; i < 2; i++) {
                mma16816(oAcc[i][0], pah[i], vh0);
                mma16816(oAcc[i][0], pal[i], vh0);
                mma16816(oAcc[i][0], pah[i], vl0);
                mma16816(oAcc[i][1], pah[i], vh1);
                mma16816(oAcc[i][1], pal[i], vh1);
                mma16816(oAcc[i][1], pah[i], vl1);
            }
        }
    }

    #pragma unroll
    for (int i = 0; i < 2; i++)
        #pragma unroll
        for (int j = 0; j < 2; j++) {
            lAcc[i][j] += __shfl_xor_sync(0xffffffffu, lAcc[i][j], 1);
            lAcc[i][j] += __shfl_xor_sync(0xffffffffu, lAcc[i][j], 2);
        }

    #pragma unroll
    for (int i = 0; i < 2; i++) {
        float inv0 = 1.f / lAcc[i][0];
        float inv1 = 1.f / lAcc[i][1];
        int r = qbase + warp*32 + i*16 + (lane >> 2);
        #pragma unroll
        for (int n = 0; n < 2; n++) {
            float* op = out + (size_t)(b*512 + r)*128 + h*16 + n*8 + c2;
            float2 lo = {oAcc[i][n].x * inv0, oAcc[i][n].y * inv0};
            float2 hi = {oAcc[i][n].z * inv1, oAcc[i][n].w * inv1};
            *(float2*)op = lo;
            *(float2*)(op + 8*128) = hi;
        }
    }
}

// ---------------- launch ----------------
extern "C" void kernel_launch(void* const* d_in, const int* in_sizes, int n_in,
                              void* d_out, int out_size) {
    const float* x     = (const float*)d_in[0];
    const int*   mask  = (const int*)  d_in[1];
    const float* ln_s  = (const float*)d_in[2];
    const float* ln_b  = (const float*)d_in[3];
    const float* dw_w  = (const float*)d_in[4];
    const float* dw_b  = (const float*)d_in[5];
    const float* pw_w  = (const float*)d_in[6];
    const float* pw_b  = (const float*)d_in[7];
    const float* Wq    = (const float*)d_in[8];
    const float* Wk    = (const float*)d_in[9];
    const float* Wv    = (const float*)d_in[10];
    const float* Wo    = (const float*)d_in[11];
    const float* ab    = (const float*)d_in[12];
    const float* f1w   = (const float*)d_in[13];
    const float* f1b   = (const float*)d_in[14];
    const float* f2w   = (const float*)d_in[15];
    const float* f2b   = (const float*)d_in[16];
    float* out = (float*)d_out;

    float *hA, *hB, *aP, *qkvP;
    u32 *wBP, *kvFP;
    cudaGetSymbolAddress((void**)&hA,   g_h);
    cudaGetSymbolAddress((void**)&hB,   g_h2);
    cudaGetSymbolAddress((void**)&aP,   g_a);
    cudaGetSymbolAddress((void**)&qkvP, g_qkv);
    cudaGetSymbolAddress((void**)&wBP,  g_wB);
    cudaGetSymbolAddress((void**)&kvFP, g_kvF);

    const int GSMEM = (16384 + 4224) * 4;       // 82432 B -> 2 blocks/SM

    auto gConv = gemmT<true,  false, 1, true,  true,  true>;
    auto gQKV  = gemmT<false, true,  2, false, false, false>;
    auto gWo   = gemmT<false, false, 2, false, true,  true>;
    auto gF1   = gemmT<false, false, 1, true,  false, false>;
    auto gF2   = gemmT<false, false, 1, false, true,  false>;
    cudaFuncSetAttribute(gConv, cudaFuncAttributeMaxDynamicSharedMemorySize, GSMEM);
    cudaFuncSetAttribute(gQKV,  cudaFuncAttributeMaxDynamicSharedMemorySize, GSMEM);
    cudaFuncSetAttribute(gWo,   cudaFuncAttributeMaxDynamicSharedMemorySize, GSMEM);
    cudaFuncSetAttribute(gF1,   cudaFuncAttributeMaxDynamicSharedMemorySize, GSMEM);
    cudaFuncSetAttribute(gF2,   cudaFuncAttributeMaxDynamicSharedMemorySize, GSMEM);

    prep_weights<<<640, 256>>>(Wq, Wk, Wv, pw_w, f1w, f2w, Wo, wBP);
    addpos_ln<<<128, 512>>>(x, out, hA, ln_s, ln_b);

    float* hin = hA; float* hob = hB;
    for (int i = 0; i < 4; i++) {
        gConv<<<256, 256, GSMEM>>>(hin, wBP + (size_t)(3+i)*16384, pw_b + i*128, out, out, hob,
                                   ln_s + (i+1)*128, ln_b + (i+1)*128,
                                   dw_w + i*896, dw_b + i*128);
        float* tmp = hin; hin = hob; hob = tmp;
    }
    // hin holds LN[4](out)
    gQKV<<<dim3(256,3), 256, GSMEM>>>(hin, wBP, ab, nullptr, qkvP, nullptr,
                                      nullptr, nullptr, nullptr, nullptr);
    kvRepack<<<dim3(2,128), 256>>>(qkvP, kvFP);
    attnT<<<dim3(4,128), 128>>>(qkvP, kvFP, mask, aP);
    gWo<<<256, 256, GSMEM>>>(aP, wBP + (size_t)9*16384, ab, out, out, hob,
                             ln_s + 5*128, ln_b + 5*128, nullptr, nullptr);
    gF1<<<256, 256, GSMEM>>>(hob, wBP + (size_t)7*16384, f1b, nullptr, aP, nullptr,
                             nullptr, nullptr, nullptr, nullptr);
    gF2<<<256, 256, GSMEM>>>(aP, wBP + (size_t)8*16384, f2b, out, out, nullptr,
                             nullptr, nullptr, nullptr, nullptr);
}